// round 8
// baseline (speedup 1.0000x reference)
#include <cuda_runtime.h>
#include <cuda_bf16.h>
#include <cstdint>

#define NN 50000
#define NE 800000
#define NV 1000
#define F 128
#define NG 64
#define NC 10
#define NSCANBLK 49

typedef unsigned int u32;
typedef unsigned long long u64;

// ---- scratch (zero at load; re-zeroed at graph end for replay determinism) ----
__device__ float    g_tl[NV * F];       // embed_table @ Wl1^T (fp32)
__device__ float    g_tr[NV * F];       // embed_table @ Wr1^T (fp32)
__device__ float    g_h1[NN * F];       // h1 fp32
__device__ float    g_agg[NN * F];      // neighbor-mean fp32
__device__ float    g_h2[NN * F];
__device__ u32      g_Wb[2][2][128 * 64]; // [kchunk][hi/lo] W bf16 pairs
__device__ int      g_deg[NN];          // 0 at graph start
__device__ int      g_off[NN + 1];
__device__ int      g_cur[NN];
__device__ int2     g_csre[NE];         // (src node, vocab id)
__device__ int      g_gcnt[NG];         // 0 at graph start
__device__ int      g_goff[NG + 1];
__device__ int      g_chain[NSCANBLK];
__device__ int      g_ready[NSCANBLK];  // 0 at graph start

__device__ __forceinline__ float bf_lo(u32 u) { return __uint_as_float(u << 16); }
__device__ __forceinline__ float bf_hi(u32 u) { return __uint_as_float(u & 0xFFFF0000u); }
__device__ __forceinline__ u32 bfpack(float lo, float hi) {
    u32 r;
    asm("cvt.rn.bf16x2.f32 %0, %1, %2;" : "=r"(r) : "f"(hi), "f"(lo));
    return r;
}
__device__ __forceinline__ void fma2(u64& acc, u64 v, u64 one2) {
    asm("fma.rn.f32x2 %0, %1, %2, %0;" : "+l"(acc) : "l"(v), "l"(one2));
}
__device__ __forceinline__ float2 unpk(u64 v) {
    float2 r;
    asm("mov.b64 {%0, %1}, %2;" : "=f"(r.x), "=f"(r.y) : "l"(v));
    return r;
}

// ================= launch 1: vocab-table dual GEMM (blocks 0..31) + counts =================
__global__ __launch_bounds__(256)
void k_count_tab(const int* __restrict__ dst, const int* __restrict__ batch,
                 const float* __restrict__ table,
                 const float* __restrict__ W1, const float* __restrict__ W2) {
    __shared__ float sA[128 * 33];
    if (blockIdx.x < 32) {
        const int node0 = blockIdx.x * 32;
        const int t = threadIdx.x;
        for (int idx = t; idx < 32 * 128; idx += 256) {
            int n = idx >> 7, k = idx & 127;
            int g = node0 + n;
            sA[k * 33 + n] = (g < NV) ? table[g * F + k] : 0.f;
        }
        __syncthreads();
        const int lane = t & 31, w = t >> 5;
        const int j0 = w * 16;
        float acc1[16], acc2[16];
#pragma unroll
        for (int jj = 0; jj < 16; jj++) { acc1[jj] = 0.f; acc2[jj] = 0.f; }
#pragma unroll 2
        for (int k0 = 0; k0 < 128; k0 += 4) {
            float a0 = sA[(k0 + 0) * 33 + lane];
            float a1 = sA[(k0 + 1) * 33 + lane];
            float a2 = sA[(k0 + 2) * 33 + lane];
            float a3 = sA[(k0 + 3) * 33 + lane];
#pragma unroll
            for (int jj = 0; jj < 16; jj++) {
                const float4 w1 = *reinterpret_cast<const float4*>(&W1[(j0 + jj) * F + k0]);
                acc1[jj] = fmaf(a0, w1.x, fmaf(a1, w1.y, fmaf(a2, w1.z, fmaf(a3, w1.w, acc1[jj]))));
                const float4 w2 = *reinterpret_cast<const float4*>(&W2[(j0 + jj) * F + k0]);
                acc2[jj] = fmaf(a0, w2.x, fmaf(a1, w2.y, fmaf(a2, w2.z, fmaf(a3, w2.w, acc2[jj]))));
            }
        }
        const int node = node0 + lane;
        if (node < NV) {
#pragma unroll
            for (int jj = 0; jj < 16; jj++) {
                g_tl[node * F + j0 + jj] = acc1[jj];
                g_tr[node * F + j0 + jj] = acc2[jj];
            }
        }
    } else {
        int i = (blockIdx.x - 32) * 256 + threadIdx.x;
        if (i < NE) atomicAdd(&g_deg[dst[i]], 1);
        if (i < NN) atomicAdd(&g_gcnt[batch[i]], 1);
    }
}

__device__ __forceinline__ int warp_incl_scan(int v) {
    int lane = threadIdx.x & 31;
#pragma unroll
    for (int d = 1; d < 32; d <<= 1) {
        int t = __shfl_up_sync(0xffffffffu, v, d);
        if (lane >= d) v += t;
    }
    return v;
}

// ================= launch 2: single-pass scan + graph offsets + W hi/lo split =================
__global__ void k_scan1(const float* __restrict__ Wl2, const float* __restrict__ Wr2) {
    int b = blockIdx.x;
    if (b >= 50) {
        int idx = (b - 50) * 1024 + threadIdx.x;
        int kc = idx >> 13, r = idx & 8191;
        int j = r >> 6, c = r & 63;
        const float* W = kc ? Wr2 : Wl2;
        float f0 = W[j * F + 2 * c], f1 = W[j * F + 2 * c + 1];
        u32 ph = bfpack(f0, f1);
        u32 pl = bfpack(f0 - bf_lo(ph), f1 - bf_hi(ph));
        g_Wb[kc][0][r] = ph;
        g_Wb[kc][1][r] = pl;
        return;
    }
    if (b == NSCANBLK) {
        if (threadIdx.x < 32) {
            int lane = threadIdx.x;
            int carry = 0;
            for (int base = 0; base < NG; base += 32) {
                int v = g_gcnt[base + lane];
                int incl = warp_incl_scan(v);
                g_goff[base + lane] = carry + incl - v;
                carry += __shfl_sync(0xffffffffu, incl, 31);
            }
            if (lane == 0) g_goff[NG] = NN;
        }
        return;
    }
    __shared__ int wsum[32];
    __shared__ int sprefix;
    int t = threadIdx.x, lane = t & 31, w = t >> 5;
    int i = b * 1024 + t;
    int v = (i < NN) ? g_deg[i] : 0;
    int incl = warp_incl_scan(v);
    if (lane == 31) wsum[w] = incl;
    __syncthreads();
    if (w == 0) wsum[lane] = warp_incl_scan(wsum[lane]);
    __syncthreads();
    if (t == 0) {
        int prefix = 0;
        if (b > 0) {
            while (((volatile int*)g_ready)[b - 1] == 0) {}
            __threadfence();
            prefix = ((volatile int*)g_chain)[b - 1];
        }
        g_chain[b] = prefix + wsum[31];
        __threadfence();
        atomicExch(&g_ready[b], 1);
        sprefix = prefix;
    }
    __syncthreads();
    int excl = sprefix + (w ? wsum[w - 1] : 0) + incl - v;
    if (i < NN) { g_off[i] = excl; g_cur[i] = excl; }
    if (i == 0) g_off[NN] = NE;
}

// ================= launch 3: CSR fill (packed int2) =================
__global__ void k_csr(const int* __restrict__ src, const int* __restrict__ dst,
                      const int* __restrict__ x_idx) {
    int i = blockIdx.x * blockDim.x + threadIdx.x;
    int stride = gridDim.x * blockDim.x;
    for (int e = i; e < NE; e += stride) {
        int s = src[e];
        int pos = atomicAdd(&g_cur[dst[e]], 1);
        g_csre[pos] = make_int2(s, x_idx[s]);
    }
}

// ================= launch 4 (PROFILED): layer-1 aggregate, packed-FFMA2 =================
__global__ void k_agg1(const int* __restrict__ x_idx, const float* __restrict__ bl1) {
    int gid = blockIdx.x * blockDim.x + threadIdx.x;
    int n = gid >> 5;
    int lane = gid & 31;
    if (n >= NN) return;
    int o0 = g_off[n], o1 = g_off[n + 1];
    const ulonglong2* tl2 = reinterpret_cast<const ulonglong2*>(g_tl);
    u64 one2;
    asm("mov.b64 %0, {%1, %1};" : "=l"(one2) : "f"(1.0f));
    u64 a01 = 0, a23 = 0;
    int e = o0;
    for (; e + 3 < o1; e += 4) {
        int v0 = g_csre[e].y, v1 = g_csre[e + 1].y;
        int v2 = g_csre[e + 2].y, v3 = g_csre[e + 3].y;
        ulonglong2 t0 = tl2[v0 * 32 + lane];
        ulonglong2 t1 = tl2[v1 * 32 + lane];
        ulonglong2 t2 = tl2[v2 * 32 + lane];
        ulonglong2 t3 = tl2[v3 * 32 + lane];
        fma2(a01, t0.x, one2); fma2(a23, t0.y, one2);
        fma2(a01, t1.x, one2); fma2(a23, t1.y, one2);
        fma2(a01, t2.x, one2); fma2(a23, t2.y, one2);
        fma2(a01, t3.x, one2); fma2(a23, t3.y, one2);
    }
    for (; e < o1; e++) {
        ulonglong2 t0 = tl2[g_csre[e].y * 32 + lane];
        fma2(a01, t0.x, one2); fma2(a23, t0.y, one2);
    }
    float2 p01 = unpk(a01), p23 = unpk(a23);
    float inv = 1.f / fmaxf((float)(o1 - o0), 1.f);
    int vs = x_idx[n];
    float4 r = reinterpret_cast<const float4*>(g_tr)[vs * 32 + lane];
    float4 b = reinterpret_cast<const float4*>(bl1)[lane];
    float4 h;
    h.x = fmaxf(fmaf(p01.x, inv, b.x + r.x), 0.f);
    h.y = fmaxf(fmaf(p01.y, inv, b.y + r.y), 0.f);
    h.z = fmaxf(fmaf(p23.x, inv, b.z + r.z), 0.f);
    h.w = fmaxf(fmaf(p23.y, inv, b.w + r.w), 0.f);
    reinterpret_cast<float4*>(g_h1)[n * 32 + lane] = h;
}

// ================= launch 5: layer-2 aggregate, packed-FFMA2 =================
__global__ void k_agg2() {
    int gid = blockIdx.x * blockDim.x + threadIdx.x;
    int n = gid >> 5;
    int lane = gid & 31;
    if (n >= NN) return;
    int o0 = g_off[n], o1 = g_off[n + 1];
    const ulonglong2* h12 = reinterpret_cast<const ulonglong2*>(g_h1);
    u64 one2;
    asm("mov.b64 %0, {%1, %1};" : "=l"(one2) : "f"(1.0f));
    u64 a01 = 0, a23 = 0;
    int e = o0;
    for (; e + 3 < o1; e += 4) {
        int s0 = g_csre[e].x, s1 = g_csre[e + 1].x;
        int s2 = g_csre[e + 2].x, s3 = g_csre[e + 3].x;
        ulonglong2 t0 = h12[s0 * 32 + lane];
        ulonglong2 t1 = h12[s1 * 32 + lane];
        ulonglong2 t2 = h12[s2 * 32 + lane];
        ulonglong2 t3 = h12[s3 * 32 + lane];
        fma2(a01, t0.x, one2); fma2(a23, t0.y, one2);
        fma2(a01, t1.x, one2); fma2(a23, t1.y, one2);
        fma2(a01, t2.x, one2); fma2(a23, t2.y, one2);
        fma2(a01, t3.x, one2); fma2(a23, t3.y, one2);
    }
    for (; e < o1; e++) {
        ulonglong2 t0 = h12[g_csre[e].x * 32 + lane];
        fma2(a01, t0.x, one2); fma2(a23, t0.y, one2);
    }
    float2 p01 = unpk(a01), p23 = unpk(a23);
    float inv = 1.f / fmaxf((float)(o1 - o0), 1.f);
    float4 o;
    o.x = p01.x * inv; o.y = p01.y * inv;
    o.z = p23.x * inv; o.w = p23.y * inv;
    reinterpret_cast<float4*>(g_agg)[n * 32 + lane] = o;
}

// ================= launch 6: HMMA GEMM: h2 = relu([agg|h1] @ [Wl2|Wr2]^T + bl2) =================
// smem (u32 units): [0..128) bias, A_hi 128x66, W_hi 128x66, W_lo 128x66  (~102KB, 2 CTA/SM)
#define SROW 66
#define OFF_AH 128
#define OFF_WH (OFF_AH + 128 * SROW)
#define OFF_WL (OFF_WH + 128 * SROW)
#define SMEM_FU ((OFF_WL + 128 * SROW) * 4)

__device__ __forceinline__ void mma_bf16(float* c, u32 a0, u32 a1, u32 a2, u32 a3,
                                         u32 b0, u32 b1) {
    asm volatile(
        "mma.sync.aligned.m16n8k16.row.col.f32.bf16.bf16.f32 "
        "{%0,%1,%2,%3}, {%4,%5,%6,%7}, {%8,%9}, {%0,%1,%2,%3};"
        : "+f"(c[0]), "+f"(c[1]), "+f"(c[2]), "+f"(c[3])
        : "r"(a0), "r"(a1), "r"(a2), "r"(a3), "r"(b0), "r"(b1));
}

__global__ __launch_bounds__(256, 2)
void k_gemm2(const float* __restrict__ bl2) {
    extern __shared__ u32 sm[];
    const int t = threadIdx.x, lane = t & 31, wid = t >> 5;
    const int node0 = blockIdx.x * 128;
    const int r = lane >> 2, q = lane & 3;
    const int m0 = wid * 16;

    if (t < 128) ((float*)sm)[t] = bl2[t];

    float acc[16][4];
#pragma unroll
    for (int nt = 0; nt < 16; nt++)
#pragma unroll
        for (int c = 0; c < 4; c++) acc[nt][c] = 0.f;

    for (int kc = 0; kc < 2; kc++) {
        // ---- stage A chunk: fp32 -> bf16 hi ----
        const float2* af = reinterpret_cast<const float2*>(kc == 0 ? g_agg : g_h1);
#pragma unroll
        for (int x = t; x < 128 * 64; x += 256) {
            int row = x >> 6, c = x & 63;
            int node = node0 + row;
            float2 v = make_float2(0.f, 0.f);
            if (node < NN) v = af[node * 64 + c];
            sm[OFF_AH + row * SROW + c] = bfpack(v.x, v.y);
        }
        // ---- stage W chunk (hi + lo) ----
        const uint2* wh = reinterpret_cast<const uint2*>(g_Wb[kc][0]);
        const uint2* wl = reinterpret_cast<const uint2*>(g_Wb[kc][1]);
#pragma unroll
        for (int x = t; x < 4096; x += 256) {
            int j = x >> 5, c2 = (x & 31) * 2;
            uint2 a = wh[x], b = wl[x];
            sm[OFF_WH + j * SROW + c2] = a.x;
            sm[OFF_WH + j * SROW + c2 + 1] = a.y;
            sm[OFF_WL + j * SROW + c2] = b.x;
            sm[OFF_WL + j * SROW + c2 + 1] = b.y;
        }
        __syncthreads();

        // ---- 2 passes (W hi, W lo) x 8 k-steps x 16 n-tiles ----
#pragma unroll
        for (int p = 0; p < 2; p++) {
            const u32* Wb = sm + ((p == 1) ? OFF_WL : OFF_WH);
#pragma unroll
            for (int ks = 0; ks < 8; ks++) {
                int kb = ks * 8 + q;
                u32 a0 = sm[OFF_AH + (m0 + r) * SROW + kb];
                u32 a1 = sm[OFF_AH + (m0 + r + 8) * SROW + kb];
                u32 a2 = sm[OFF_AH + (m0 + r) * SROW + kb + 4];
                u32 a3 = sm[OFF_AH + (m0 + r + 8) * SROW + kb + 4];
#pragma unroll
                for (int nt = 0; nt < 16; nt++) {
                    u32 b0 = Wb[(nt * 8 + r) * SROW + kb];
                    u32 b1 = Wb[(nt * 8 + r) * SROW + kb + 4];
                    mma_bf16(acc[nt], a0, a1, a2, a3, b0, b1);
                }
            }
        }
        __syncthreads();
    }

    // ---- epilogue ----
    const float* sbias = (const float*)sm;
    int n0 = node0 + m0 + r;
    int n1 = n0 + 8;
#pragma unroll
    for (int nt = 0; nt < 16; nt++) {
        int col = nt * 8 + q * 2;
        float b0 = sbias[col], b1 = sbias[col + 1];
        if (n0 < NN) {
            float2 o;
            o.x = fmaxf(acc[nt][0] + b0, 0.f);
            o.y = fmaxf(acc[nt][1] + b1, 0.f);
            *reinterpret_cast<float2*>(&g_h2[n0 * F + col]) = o;
        }
        if (n1 < NN) {
            float2 o;
            o.x = fmaxf(acc[nt][2] + b0, 0.f);
            o.y = fmaxf(acc[nt][3] + b1, 0.f);
            *reinterpret_cast<float2*>(&g_h2[n1 * F + col]) = o;
        }
    }
}

// ================= launch 7: pool + classifier + re-zero counters =================
__global__ void k_poolout(const float* __restrict__ linW, const float* __restrict__ linb,
                          float* __restrict__ out) {
    if (blockIdx.x >= NG) {
        int gid = (blockIdx.x - NG) * 256 + threadIdx.x;
        int stride = (gridDim.x - NG) * 256;
        for (int x = gid; x < NN; x += stride) g_deg[x] = 0;
        for (int x = gid; x < NG; x += stride) g_gcnt[x] = 0;
        for (int x = gid; x < NSCANBLK; x += stride) g_ready[x] = 0;
        return;
    }
    __shared__ float4 red[8][32];
    __shared__ float sp[128];
    int g = blockIdx.x;
    int s = g_goff[g], e = g_goff[g + 1];
    int lane = threadIdx.x & 31, w = threadIdx.x >> 5;
    const float4* h4 = reinterpret_cast<const float4*>(g_h2);
    float4 acc = make_float4(0.f, 0.f, 0.f, 0.f);
    for (int n = s + w; n < e; n += 8) {
        float4 v = h4[n * 32 + lane];
        acc.x += v.x; acc.y += v.y; acc.z += v.z; acc.w += v.w;
    }
    red[w][lane] = acc;
    __syncthreads();
    if (w == 0) {
        float4 a = red[0][lane];
#pragma unroll
        for (int i = 1; i < 8; i++) {
            float4 b = red[i][lane];
            a.x += b.x; a.y += b.y; a.z += b.z; a.w += b.w;
        }
        float inv = 1.f / fmaxf((float)(e - s), 1.f);
        sp[lane * 4 + 0] = a.x * inv;
        sp[lane * 4 + 1] = a.y * inv;
        sp[lane * 4 + 2] = a.z * inv;
        sp[lane * 4 + 3] = a.w * inv;
    }
    __syncthreads();
    for (int c = w; c < NC; c += 8) {
        float sdot = 0.f;
        for (int k = lane; k < F; k += 32) sdot += sp[k] * linW[c * F + k];
#pragma unroll
        for (int d = 16; d > 0; d >>= 1) sdot += __shfl_down_sync(0xffffffffu, sdot, d);
        if (lane == 0) out[g * NC + c] = sdot + linb[c];
    }
}

extern "C" void kernel_launch(void* const* d_in, const int* in_sizes, int n_in,
                              void* d_out, int out_size) {
    const int*   x_idx = (const int*)d_in[0];
    const int*   eidx  = (const int*)d_in[1];
    const int*   batch = (const int*)d_in[2];
    const float* table = (const float*)d_in[3];
    const float* Wl1   = (const float*)d_in[4];
    const float* bl1   = (const float*)d_in[5];
    const float* Wr1   = (const float*)d_in[6];
    const float* Wl2   = (const float*)d_in[7];
    const float* bl2   = (const float*)d_in[8];
    const float* Wr2   = (const float*)d_in[9];
    const float* linW  = (const float*)d_in[10];
    const float* linb  = (const float*)d_in[11];
    float* out = (float*)d_out;

    const int* src = eidx;
    const int* dst = eidx + NE;

    static int smem_set = 0;
    if (!smem_set) {
        cudaFuncSetAttribute(k_gemm2, cudaFuncAttributeMaxDynamicSharedMemorySize, SMEM_FU);
        smem_set = 1;
    }

    k_count_tab<<<32 + (NE + 255) / 256, 256>>>(dst, batch, table, Wl1, Wr1);
    k_scan1<<<66, 1024>>>(Wl2, Wr2);
    k_csr<<<3125, 256>>>(src, dst, x_idx);
    k_agg1<<<(NN * 32 + 255) / 256, 256>>>(x_idx, bl1);      // 4th launch: profiled
    k_agg2<<<(NN * 32 + 255) / 256, 256>>>();
    k_gemm2<<<(NN + 127) / 128, 256, SMEM_FU>>>(bl2);
    k_poolout<<<NG + 197, 256>>>(linW, linb, out);
}